// round 10
// baseline (speedup 1.0000x reference)
#include <cuda_runtime.h>
#include <cuda_bf16.h>
#include <cstdint>

// Problem constants
#define BS     64
#define NSTK   64
#define NHALF  32
#define COORD  32
#define SPEMB  256
#define DNIN   128
#define DNOUT  256
#define NPNT   64
#define QOUT   32
#define KTOT   (DNIN*3)              // 384
#define NTOTPNT (NSTK*NPNT)          // 4096
#define YTOT   (BS*DNOUT*NHALF*QOUT) // 16777216

// GEMM: Y[256,65536] = W[256,384] x B[384,65536]
// K reordered as k = kk*128 + i. 6 physical chunks of 64 (kk = c>>1, i0 = (c&1)*64).
// Per chunk: 3 mma passes (Ah*Bh, Al*Bh, Ah*Bl) into shared accumulators.
// CTA tile M=128 x N=128 (grid = 512 ntiles x 2 mtiles). Stage 64KB, double-buffered.
#define NTILES 512                   // (b, sg): 128 n = 4 strokes x 32 q
#define NCHUNK 6
// stage layout: Ah 16K | Al 16K | Bh 16K | Bl 16K
#define STAGE_BYTES 65536
#define SMEM_GEMM (2*STAGE_BYTES)    // 131072 (epilogue Ds 67584 reuses)

// Scratch (device globals; no allocation allowed)
__device__ int   g_idx[BS*NHALF];
// A blobs [12][2 mt][128 m][64 i] bf16: j<6 hi, j>=6 lo; per (j,mt) 16KB
__device__ __align__(16) __nv_bfloat16 g_Ab[12*2*128*64];    // 384 KB
__device__ float g_y[YTOT];
__device__ float g_ps[DNOUT*NTILES];
__device__ float g_pq[DNOUT*NTILES];
__device__ float g_mean[DNOUT];
__device__ float g_rstd[DNOUT];

// ---------------------------------------------------------------------------
// helpers
// ---------------------------------------------------------------------------
__device__ __forceinline__ uint32_t smem_u32(const void* p) {
    uint32_t a;
    asm("{ .reg .u64 t; cvta.to.shared.u64 t, %1; cvt.u32.u64 %0, t; }" : "=r"(a) : "l"(p));
    return a;
}
__device__ __forceinline__ void cp16(uint32_t dst, const void* src) {
    asm volatile("cp.async.cg.shared.global [%0], [%1], 16;\n" :: "r"(dst), "l"(src));
}
__device__ __forceinline__ void ldsm_x4(uint32_t addr, uint32_t* r) {
    asm volatile("ldmatrix.sync.aligned.m8n8.x4.shared.b16 {%0,%1,%2,%3}, [%4];"
        : "=r"(r[0]), "=r"(r[1]), "=r"(r[2]), "=r"(r[3]) : "r"(addr));
}
__device__ __forceinline__ void mma16816(float* d, const uint32_t* a, uint32_t b0, uint32_t b1) {
    asm volatile("mma.sync.aligned.m16n8k16.row.col.f32.bf16.bf16.f32 "
        "{%0,%1,%2,%3}, {%4,%5,%6,%7}, {%8,%9}, {%0,%1,%2,%3};"
        : "+f"(d[0]), "+f"(d[1]), "+f"(d[2]), "+f"(d[3])
        : "r"(a[0]), "r"(a[1]), "r"(a[2]), "r"(a[3]), "r"(b0), "r"(b1));
}

// ---------------------------------------------------------------------------
// 1) FPS (matches JAX semantics: far0=0, min-dist, first-max argmax)
// ---------------------------------------------------------------------------
__global__ void fps_kernel(const float* __restrict__ coor) {
    int b = blockIdx.x;
    int j = threadIdx.x;
    __shared__ float sx[NSTK][COORD + 1];
    __shared__ float sd[NSTK];
    __shared__ int   far;

    const float* base = coor + (size_t)b * NSTK * COORD;
    #pragma unroll
    for (int c = 0; c < COORD; c++) sx[j][c] = base[j * COORD + c];
    sd[j] = 1e10f;
    if (j == 0) far = 0;
    __syncthreads();

    for (int i = 0; i < NHALF; i++) {
        int f = far;
        if (j == 0) g_idx[b * NHALF + i] = f;
        float d = 0.f;
        #pragma unroll
        for (int c = 0; c < COORD; c++) {
            float t = sx[j][c] - sx[f][c];
            d += t * t;
        }
        sd[j] = fminf(sd[j], d);
        __syncthreads();
        if (j == 0) {
            float best = sd[0]; int bi = 0;
            #pragma unroll 4
            for (int k = 1; k < NSTK; k++)
                if (sd[k] > best) { best = sd[k]; bi = k; }
            far = bi;
        }
        __syncthreads();
    }
}

// ---------------------------------------------------------------------------
// 2/3) gathers
// ---------------------------------------------------------------------------
__global__ void gather_sparse_kernel(const float* __restrict__ sf, float* __restrict__ out) {
    int t = blockIdx.x * blockDim.x + threadIdx.x;
    if (t >= BS * SPEMB * NHALF) return;
    int s = t % NHALF;
    int e = (t / NHALF) % SPEMB;
    int b = t / (NHALF * SPEMB);
    out[t] = sf[((size_t)b * SPEMB + e) * NSTK + g_idx[b * NHALF + s]];
}
__global__ void gather_coor_kernel(const float* __restrict__ coor, float* __restrict__ out) {
    int t = blockIdx.x * blockDim.x + threadIdx.x;
    if (t >= BS * NHALF * COORD) return;
    int c = t % COORD;
    int s = (t / COORD) % NHALF;
    int b = t / (COORD * NHALF);
    out[t] = coor[((size_t)b * NSTK + g_idx[b * NHALF + s]) * COORD + c];
}

// ---------------------------------------------------------------------------
// 4) Weight split -> A blobs [12][2][128 m][64 i] bf16 (k-reordered).
//    blob (j, mt), jc = j%6: kk = jc>>1, i0 = (jc&1)*64;
//    A[m][i] = w[(mt*128+m)*384 + (i0+i)*3 + kk]; j<6: hi, j>=6: lo.
// ---------------------------------------------------------------------------
__global__ void wsplit_kernel(const float* __restrict__ w) {
    int blk = blockIdx.x;           // 0..23 = j*2 + mt
    int j   = blk >> 1;
    int mt  = blk & 1;
    int jc  = j % 6;
    int kk  = jc >> 1;
    int i0  = (jc & 1) * 64;
    __nv_bfloat16* blob = g_Ab + (size_t)blk * (128 * 64);
    for (int e = threadIdx.x; e < 128 * 64; e += 256) {
        int m  = e >> 6;
        int il = e & 63;
        float val = w[(size_t)(mt * 128 + m) * KTOT + (i0 + il) * 3 + kk];
        __nv_bfloat16 hv = __float2bfloat16(val);
        blob[e] = (j < 6) ? hv : __float2bfloat16(val - __bfloat162float(hv));
    }
}

// ---------------------------------------------------------------------------
// 5) Fused im2col + mma.sync bf16 GEMM. CTA tile M=128 x N=128.
//    6 physical K chunks; per chunk 3 passes (Ah*Bh, Al*Bh, Ah*Bl).
//    A via cp.async (double-buffered); B built in smem from dense_fea.
// ---------------------------------------------------------------------------
__global__ void __launch_bounds__(256, 1) gemm_kernel(const float* __restrict__ dense,
                                                      const float* __restrict__ bias) {
    extern __shared__ char sm[];
    const uint32_t smb = smem_u32(sm);
    const int nt   = blockIdx.x;
    const int mt   = blockIdx.y;
    const int b    = nt >> 3;
    const int sg   = nt & 7;
    const int tid  = threadIdx.x;
    const int wid  = tid >> 5;
    const int lane = tid & 31;
    const int mg   = wid & 3;     // m base = mg*32
    const int ng   = wid >> 2;    // n base = ng*64

    int idx4[4];
    #pragma unroll
    for (int s = 0; s < 4; s++) idx4[s] = g_idx[b * NHALF + sg * 4 + s];

    // A loader: chunk c -> stage c&1 (Ah at +0, Al at +16384), XOR-16B swizzle
    auto loadA = [&](int c) {
        const char* srcH = (const char*)(g_Ab + ((size_t)(c * 2 + mt)) * (128 * 64));
        const char* srcL = (const char*)(g_Ab + ((size_t)((6 + c) * 2 + mt)) * (128 * 64));
        uint32_t aB = smb + (c & 1) * STAGE_BYTES;
        #pragma unroll
        for (int jj = 0; jj < 4; jj++) {        // 1024 x 16B per blob
            int f = tid + jj * 256;
            int row = f >> 3, g = f & 7;
            uint32_t off = row * 128 + ((g * 16) ^ ((row & 7) * 16));
            cp16(aB + off,         srcH + f * 16);
            cp16(aB + 16384 + off, srcL + f * 16);
        }
        asm volatile("cp.async.commit_group;\n");
    };

    // B builder: chunk c -> stage c&1: Bh at +32768, Bl at +49152.
    // B[n][il] = X[b, i0+il, idx4[n>>5]*64 + 2*(n&31) + kk - 1]; left zero pad only.
    auto buildB = [&](int c) {
        int kk = c >> 1;
        int i0 = (c & 1) * 64;
        char* bH = sm + (c & 1) * STAGE_BYTES + 32768;
        #pragma unroll
        for (int jj = 0; jj < 32; jj++) {
            int e  = tid + jj * 256;
            int il = e >> 7;
            int n  = e & 127;
            int s_l = n >> 5, q = n & 31;
            int p = 2 * q + kk - 1;
            float val = 0.f;
            if (p >= 0)
                val = dense[((size_t)(b * DNIN + i0 + il)) * NTOTPNT + idx4[s_l] * NPNT + p];
            __nv_bfloat16 hv = __float2bfloat16(val);
            __nv_bfloat16 lv = __float2bfloat16(val - __bfloat162float(hv));
            uint32_t sw = n * 128 + ((il * 2) ^ ((n & 7) * 16));
            *(__nv_bfloat16*)(bH + sw)         = hv;
            *(__nv_bfloat16*)(bH + 16384 + sw) = lv;
        }
    };

    float acc[2][8][4];
    #pragma unroll
    for (int mi = 0; mi < 2; mi++)
        #pragma unroll
        for (int n8 = 0; n8 < 8; n8++)
            #pragma unroll
            for (int r = 0; r < 4; r++) acc[mi][n8][r] = 0.f;

    loadA(0);
    loadA(1);
    buildB(0);
    asm volatile("cp.async.wait_group 1;" ::: "memory");   // A(0) done
    __syncthreads();

    const int rowSel = lane & 15;
    const int kSel   = (lane >> 4) * 16;

    #pragma unroll 1
    for (int c = 0; c < NCHUNK; c++) {
        const uint32_t sb = smb + (c & 1) * STAGE_BYTES;
        #pragma unroll 1
        for (int pass = 0; pass < 3; pass++) {
            const uint32_t aB = sb + ((pass == 1) ? 16384u : 0u);
            const uint32_t bB = sb + 32768u + ((pass == 2) ? 16384u : 0u);
            #pragma unroll
            for (int kb = 0; kb < 4; kb++) {
                uint32_t A[2][4], Bf[4][4];
                #pragma unroll
                for (int mi = 0; mi < 2; mi++) {
                    int row = mg * 32 + mi * 16 + rowSel;
                    ldsm_x4(aB + row * 128 + ((kb * 32 + kSel) ^ ((row & 7) * 16)), A[mi]);
                }
                #pragma unroll
                for (int np = 0; np < 4; np++) {
                    int row = ng * 64 + np * 16 + rowSel;
                    ldsm_x4(bB + row * 128 + ((kb * 32 + kSel) ^ ((row & 7) * 16)), Bf[np]);
                }
                #pragma unroll
                for (int mi = 0; mi < 2; mi++)
                    #pragma unroll
                    for (int n8 = 0; n8 < 8; n8++)
                        mma16816(acc[mi][n8], A[mi],
                                 Bf[n8 >> 1][n8 & 1], Bf[n8 >> 1][(n8 & 1) + 2]);
            }
        }
        __syncthreads();    // done reading stage c&1 (about to be overwritten)
        if (c < NCHUNK - 1) {
            if (c < NCHUNK - 2) loadA(c + 2);     // into stage c&1 (now free)
            buildB(c + 1);                        // into stage (c+1)&1
            if (c < NCHUNK - 2)
                asm volatile("cp.async.wait_group 1;" ::: "memory");  // A(c+1) done
            else
                asm volatile("cp.async.wait_group 0;" ::: "memory");
            __syncthreads();
        }
    }

    // ---- epilogue: fragments -> smem Ds[128][132], then coalesced out + BN
    float* Ds = (float*)sm;
    #pragma unroll
    for (int mi = 0; mi < 2; mi++) {
        int row0 = mg * 32 + mi * 16 + (lane >> 2);
        #pragma unroll
        for (int n8 = 0; n8 < 8; n8++) {
            int col = ng * 64 + n8 * 8 + (lane & 3) * 2;
            Ds[row0 * 132 + col]           = acc[mi][n8][0];
            Ds[row0 * 132 + col + 1]       = acc[mi][n8][1];
            Ds[(row0 + 8) * 132 + col]     = acc[mi][n8][2];
            Ds[(row0 + 8) * 132 + col + 1] = acc[mi][n8][3];
        }
    }
    __syncthreads();

    for (int it = 0; it < 16; it++) {
        int m = it * 8 + wid;            // 0..127 local row
        int o = mt * 128 + m;            // global output channel
        float bo = __ldg(bias + o);
        float4 v = *(float4*)(Ds + m * 132 + lane * 4);
        v.x += bo; v.y += bo; v.z += bo; v.w += bo;
        *(float4*)(g_y + ((size_t)(b * DNOUT + o)) * 1024 + sg * 128 + lane * 4) = v;
        float s1 = v.x + v.y + v.z + v.w;
        float s2 = v.x * v.x + v.y * v.y + v.z * v.z + v.w * v.w;
        #pragma unroll
        for (int d = 16; d > 0; d >>= 1) {
            s1 += __shfl_xor_sync(0xffffffffu, s1, d);
            s2 += __shfl_xor_sync(0xffffffffu, s2, d);
        }
        if (lane == 0) {
            g_ps[o * NTILES + nt] = s1;
            g_pq[o * NTILES + nt] = s2;
        }
    }
}

// ---------------------------------------------------------------------------
// 6) BN stats finalize
// ---------------------------------------------------------------------------
__global__ void bnstat_kernel() {
    int o = blockIdx.x;
    int t = threadIdx.x;
    float s1 = 0.f, s2 = 0.f;
    for (int k = t; k < NTILES; k += 256) {
        s1 += g_ps[o * NTILES + k];
        s2 += g_pq[o * NTILES + k];
    }
    __shared__ float a[256], c[256];
    a[t] = s1; c[t] = s2;
    __syncthreads();
    for (int st = 128; st > 0; st >>= 1) {
        if (t < st) { a[t] += a[t + st]; c[t] += c[t + st]; }
        __syncthreads();
    }
    if (t == 0) {
        const float N = (float)(BS * NHALF * QOUT);
        float mean = a[0] / N;
        float var  = c[0] / N - mean * mean;
        g_mean[o] = mean;
        g_rstd[o] = rsqrtf(var + 1e-5f);
    }
}

// ---------------------------------------------------------------------------
// 7) Normalize + affine + tanh-GELU
// ---------------------------------------------------------------------------
__device__ __forceinline__ float gelu_tanh(float x) {
    float x3 = x * x * x;
    return 0.5f * x * (1.f + tanhf(0.7978845608028654f * (x + 0.044715f * x3)));
}
__global__ void norm_kernel(const float* __restrict__ gamma,
                            const float* __restrict__ beta,
                            float* __restrict__ out)
{
    const int TOT4 = YTOT / 4;
    int t = blockIdx.x * blockDim.x + threadIdx.x;
    if (t >= TOT4) return;
    int o = (t >> 8) & (DNOUT - 1);
    float r  = g_rstd[o];
    float m  = g_mean[o];
    float g  = gamma[o] * r;
    float bb = beta[o] - m * g;
    float4 v = ((const float4*)g_y)[t];
    float4 w;
    w.x = gelu_tanh(v.x * g + bb);
    w.y = gelu_tanh(v.y * g + bb);
    w.z = gelu_tanh(v.z * g + bb);
    w.w = gelu_tanh(v.w * g + bb);
    ((float4*)out)[t] = w;
}

// ---------------------------------------------------------------------------
// Launch
// ---------------------------------------------------------------------------
extern "C" void kernel_launch(void* const* d_in, const int* in_sizes, int n_in,
                              void* d_out, int out_size)
{
    const float* sparse_fea = (const float*)d_in[0];  // [64,256,64]
    const float* dense_fea  = (const float*)d_in[1];  // [64,128,4096]
    const float* stk_coor   = (const float*)d_in[2];  // [64,64,32]
    const float* conv_w     = (const float*)d_in[3];  // [256,128,1,3]
    const float* conv_b     = (const float*)d_in[4];  // [256]
    const float* bn_gamma   = (const float*)d_in[5];  // [256]
    const float* bn_beta    = (const float*)d_in[6];  // [256]

    float* out_sparse = (float*)d_out;
    float* out_dense  = out_sparse + BS * SPEMB * NHALF;
    float* out_coor   = out_dense + YTOT;

    cudaFuncSetAttribute(gemm_kernel,
                         cudaFuncAttributeMaxDynamicSharedMemorySize, SMEM_GEMM);

    fps_kernel<<<BS, NSTK>>>(stk_coor);
    wsplit_kernel<<<24, 256>>>(conv_w);

    gather_sparse_kernel<<<(BS * SPEMB * NHALF + 255) / 256, 256>>>(sparse_fea, out_sparse);
    gather_coor_kernel<<<(BS * NHALF * COORD + 255) / 256, 256>>>(stk_coor, out_coor);

    dim3 ggrid(NTILES, 2);
    gemm_kernel<<<ggrid, 256, SMEM_GEMM>>>(dense_fea, conv_b);

    bnstat_kernel<<<DNOUT, 256>>>();
    norm_kernel<<<(YTOT / 4 + 255) / 256, 256>>>(bn_gamma, bn_beta, out_dense);
}

// round 11
// speedup vs baseline: 1.2484x; 1.2484x over previous
#include <cuda_runtime.h>
#include <cuda_bf16.h>
#include <cstdint>

// Problem constants
#define BS     64
#define NSTK   64
#define NHALF  32
#define COORD  32
#define SPEMB  256
#define DNIN   128
#define DNOUT  256
#define NPNT   64
#define QOUT   32
#define KTOT   (DNIN*3)              // 384
#define NTOTPNT (NSTK*NPNT)          // 4096
#define YTOT   (BS*DNOUT*NHALF*QOUT) // 16777216

// GEMM: Y[256,65536] = W[256,384] x B[384,65536]
// K reordered as k = kk*128 + i. 6 physical chunks of 64 (kk = c>>1, i0 = (c&1)*64).
// Per chunk: 3 mma passes (Ah*Bh, Al*Bh, Ah*Bl) into shared accumulators.
// CTA tile M=128 x N=128 (grid = 512 ntiles x 2 mtiles).
// smem: A double-buffered 2x32KB + B single 32KB = 96KB -> 2 CTAs/SM.
#define NTILES 512                   // (b, sg): 128 n = 4 strokes x 32 q
#define NCHUNK 6
#define SMEM_GEMM 98304              // 96KB (epilogue Ds 67584 reuses)

// Scratch (device globals; no allocation allowed)
__device__ int   g_idx[BS*NHALF];
// A blobs [12][2 mt][128 m][64 i] bf16: j<6 hi, j>=6 lo; per (j,mt) 16KB
__device__ __align__(16) __nv_bfloat16 g_Ab[12*2*128*64];    // 384 KB
__device__ float g_y[YTOT];
__device__ float g_ps[DNOUT*NTILES];
__device__ float g_pq[DNOUT*NTILES];
__device__ float g_mean[DNOUT];
__device__ float g_rstd[DNOUT];

// ---------------------------------------------------------------------------
// helpers
// ---------------------------------------------------------------------------
__device__ __forceinline__ uint32_t smem_u32(const void* p) {
    uint32_t a;
    asm("{ .reg .u64 t; cvta.to.shared.u64 t, %1; cvt.u32.u64 %0, t; }" : "=r"(a) : "l"(p));
    return a;
}
__device__ __forceinline__ void cp16(uint32_t dst, const void* src) {
    asm volatile("cp.async.cg.shared.global [%0], [%1], 16;\n" :: "r"(dst), "l"(src));
}
__device__ __forceinline__ void ldsm_x4(uint32_t addr, uint32_t* r) {
    asm volatile("ldmatrix.sync.aligned.m8n8.x4.shared.b16 {%0,%1,%2,%3}, [%4];"
        : "=r"(r[0]), "=r"(r[1]), "=r"(r[2]), "=r"(r[3]) : "r"(addr));
}
__device__ __forceinline__ void mma16816(float* d, const uint32_t* a, uint32_t b0, uint32_t b1) {
    asm volatile("mma.sync.aligned.m16n8k16.row.col.f32.bf16.bf16.f32 "
        "{%0,%1,%2,%3}, {%4,%5,%6,%7}, {%8,%9}, {%0,%1,%2,%3};"
        : "+f"(d[0]), "+f"(d[1]), "+f"(d[2]), "+f"(d[3])
        : "r"(a[0]), "r"(a[1]), "r"(a[2]), "r"(a[3]), "r"(b0), "r"(b1));
}
__device__ __forceinline__ uint32_t pack_bf16x2(float lo16, float hi16) {
    __nv_bfloat162 h = __floats2bfloat162_rn(lo16, hi16);   // x=lower addr, y=upper
    return *(uint32_t*)&h;
}

// ---------------------------------------------------------------------------
// 1) FPS (matches JAX semantics: far0=0, min-dist, first-max argmax)
// ---------------------------------------------------------------------------
__global__ void fps_kernel(const float* __restrict__ coor) {
    int b = blockIdx.x;
    int j = threadIdx.x;
    __shared__ float sx[NSTK][COORD + 1];
    __shared__ float sd[NSTK];
    __shared__ int   far;

    const float* base = coor + (size_t)b * NSTK * COORD;
    #pragma unroll
    for (int c = 0; c < COORD; c++) sx[j][c] = base[j * COORD + c];
    sd[j] = 1e10f;
    if (j == 0) far = 0;
    __syncthreads();

    for (int i = 0; i < NHALF; i++) {
        int f = far;
        if (j == 0) g_idx[b * NHALF + i] = f;
        float d = 0.f;
        #pragma unroll
        for (int c = 0; c < COORD; c++) {
            float t = sx[j][c] - sx[f][c];
            d += t * t;
        }
        sd[j] = fminf(sd[j], d);
        __syncthreads();
        if (j == 0) {
            float best = sd[0]; int bi = 0;
            #pragma unroll 4
            for (int k = 1; k < NSTK; k++)
                if (sd[k] > best) { best = sd[k]; bi = k; }
            far = bi;
        }
        __syncthreads();
    }
}

// ---------------------------------------------------------------------------
// 2/3) gathers
// ---------------------------------------------------------------------------
__global__ void gather_sparse_kernel(const float* __restrict__ sf, float* __restrict__ out) {
    int t = blockIdx.x * blockDim.x + threadIdx.x;
    if (t >= BS * SPEMB * NHALF) return;
    int s = t % NHALF;
    int e = (t / NHALF) % SPEMB;
    int b = t / (NHALF * SPEMB);
    out[t] = sf[((size_t)b * SPEMB + e) * NSTK + g_idx[b * NHALF + s]];
}
__global__ void gather_coor_kernel(const float* __restrict__ coor, float* __restrict__ out) {
    int t = blockIdx.x * blockDim.x + threadIdx.x;
    if (t >= BS * NHALF * COORD) return;
    int c = t % COORD;
    int s = (t / COORD) % NHALF;
    int b = t / (COORD * NHALF);
    out[t] = coor[((size_t)b * NSTK + g_idx[b * NHALF + s]) * COORD + c];
}

// ---------------------------------------------------------------------------
// 4) Weight split -> A blobs [12][2][128 m][64 i] bf16 (k-reordered).
//    blob (j, mt), jc = j%6: kk = jc>>1, i0 = (jc&1)*64;
//    A[m][i] = w[(mt*128+m)*384 + (i0+i)*3 + kk]; j<6: hi, j>=6: lo.
// ---------------------------------------------------------------------------
__global__ void wsplit_kernel(const float* __restrict__ w) {
    int blk = blockIdx.x;           // 0..23 = j*2 + mt
    int j   = blk >> 1;
    int mt  = blk & 1;
    int jc  = j % 6;
    int kk  = jc >> 1;
    int i0  = (jc & 1) * 64;
    __nv_bfloat16* blob = g_Ab + (size_t)blk * (128 * 64);
    for (int e = threadIdx.x; e < 128 * 64; e += 256) {
        int m  = e >> 6;
        int il = e & 63;
        float val = w[(size_t)(mt * 128 + m) * KTOT + (i0 + il) * 3 + kk];
        __nv_bfloat16 hv = __float2bfloat16(val);
        blob[e] = (j < 6) ? hv : __float2bfloat16(val - __bfloat162float(hv));
    }
}

// ---------------------------------------------------------------------------
// 5) Fused im2col + mma.sync bf16 GEMM. CTA tile M=128 x N=128, 2 CTAs/SM.
//    smem: [0,64K) A stages 0/1 (Ah+Al each), [64K,96K) B (Bh+Bl).
// ---------------------------------------------------------------------------
__global__ void __launch_bounds__(256, 2) gemm_kernel(const float* __restrict__ dense,
                                                      const float* __restrict__ bias) {
    extern __shared__ char sm[];
    const uint32_t smb = smem_u32(sm);
    const int nt   = blockIdx.x;
    const int mt   = blockIdx.y;
    const int b    = nt >> 3;
    const int sg   = nt & 7;
    const int tid  = threadIdx.x;
    const int wid  = tid >> 5;
    const int lane = tid & 31;
    const int mg   = wid & 3;     // m base = mg*32
    const int ng   = wid >> 2;    // n base = ng*64

    int idx4[4];
    #pragma unroll
    for (int s = 0; s < 4; s++) idx4[s] = g_idx[b * NHALF + sg * 4 + s];

    // A loader: chunk c -> stage c&1 at (c&1)*32768 (Ah +0, Al +16384)
    auto loadA = [&](int c) {
        const char* srcH = (const char*)(g_Ab + ((size_t)(c * 2 + mt)) * (128 * 64));
        const char* srcL = (const char*)(g_Ab + ((size_t)((6 + c) * 2 + mt)) * (128 * 64));
        uint32_t aB = smb + (c & 1) * 32768;
        #pragma unroll
        for (int jj = 0; jj < 4; jj++) {        // 1024 x 16B per blob
            int f = tid + jj * 256;
            int row = f >> 3, g = f & 7;
            uint32_t off = row * 128 + ((g * 16) ^ ((row & 7) * 16));
            cp16(aB + off,         srcH + f * 16);
            cp16(aB + 16384 + off, srcL + f * 16);
        }
        asm volatile("cp.async.commit_group;\n");
    };

    // B builder -> Bh at +65536, Bl at +81920. Thread does an (il, il+1) bf16x2 pair.
    // B[n][il] = X[b, i0+il, idx4[n>>5]*64 + 2*(n&31) + kk - 1]; left zero pad only.
    auto buildB = [&](int c) {
        int kk = c >> 1;
        int i0 = (c & 1) * 64;
        char* bH = sm + 65536;
        #pragma unroll
        for (int jj = 0; jj < 16; jj++) {
            int e   = tid + jj * 256;        // 0..4095
            int il2 = e >> 7;                // 0..31 -> il = 2*il2
            int n   = e & 127;
            int s_l = n >> 5, q = n & 31;
            int p = 2 * q + kk - 1;
            float v0 = 0.f, v1 = 0.f;
            if (p >= 0) {
                const float* xr = dense + ((size_t)(b * DNIN + i0 + 2 * il2)) * NTOTPNT
                                 + idx4[s_l] * NPNT + p;
                v0 = xr[0];
                v1 = xr[NTOTPNT];
            }
            float h0 = __bfloat162float(__float2bfloat16(v0));
            float h1 = __bfloat162float(__float2bfloat16(v1));
            uint32_t sw = n * 128 + ((il2 * 4) ^ ((n & 7) * 16));
            *(uint32_t*)(bH + sw)         = pack_bf16x2(h0, h1);
            *(uint32_t*)(bH + 16384 + sw) = pack_bf16x2(v0 - h0, v1 - h1);
        }
    };

    float acc[2][8][4];
    #pragma unroll
    for (int mi = 0; mi < 2; mi++)
        #pragma unroll
        for (int n8 = 0; n8 < 8; n8++)
            #pragma unroll
            for (int r = 0; r < 4; r++) acc[mi][n8][r] = 0.f;

    loadA(0);
    loadA(1);
    buildB(0);
    asm volatile("cp.async.wait_group 1;" ::: "memory");   // A(0) done
    __syncthreads();

    const int rowSel = lane & 15;
    const int kSel   = (lane >> 4) * 16;

    #pragma unroll 1
    for (int c = 0; c < NCHUNK; c++) {
        const uint32_t aS = smb + (c & 1) * 32768;
        #pragma unroll 1
        for (int pass = 0; pass < 3; pass++) {
            const uint32_t aB = aS + ((pass == 1) ? 16384u : 0u);
            const uint32_t bB = smb + 65536u + ((pass == 2) ? 16384u : 0u);
            #pragma unroll
            for (int kb = 0; kb < 4; kb++) {
                uint32_t A[2][4], Bf[4][4];
                #pragma unroll
                for (int mi = 0; mi < 2; mi++) {
                    int row = mg * 32 + mi * 16 + rowSel;
                    ldsm_x4(aB + row * 128 + ((kb * 32 + kSel) ^ ((row & 7) * 16)), A[mi]);
                }
                #pragma unroll
                for (int np = 0; np < 4; np++) {
                    int row = ng * 64 + np * 16 + rowSel;
                    ldsm_x4(bB + row * 128 + ((kb * 32 + kSel) ^ ((row & 7) * 16)), Bf[np]);
                }
                #pragma unroll
                for (int mi = 0; mi < 2; mi++)
                    #pragma unroll
                    for (int n8 = 0; n8 < 8; n8++)
                        mma16816(acc[mi][n8], A[mi],
                                 Bf[n8 >> 1][n8 & 1], Bf[n8 >> 1][(n8 & 1) + 2]);
            }
        }
        __syncthreads();    // B + A stage c&1 free
        if (c < NCHUNK - 1) {
            if (c < NCHUNK - 2) loadA(c + 2);     // into stage c&1 (now free)
            buildB(c + 1);
            if (c < NCHUNK - 2)
                asm volatile("cp.async.wait_group 1;" ::: "memory");  // A(c+1) done
            else
                asm volatile("cp.async.wait_group 0;" ::: "memory");
            __syncthreads();
        }
    }

    // ---- epilogue: fragments -> smem Ds[128][132], then coalesced out + BN
    float* Ds = (float*)sm;
    #pragma unroll
    for (int mi = 0; mi < 2; mi++) {
        int row0 = mg * 32 + mi * 16 + (lane >> 2);
        #pragma unroll
        for (int n8 = 0; n8 < 8; n8++) {
            int col = ng * 64 + n8 * 8 + (lane & 3) * 2;
            Ds[row0 * 132 + col]           = acc[mi][n8][0];
            Ds[row0 * 132 + col + 1]       = acc[mi][n8][1];
            Ds[(row0 + 8) * 132 + col]     = acc[mi][n8][2];
            Ds[(row0 + 8) * 132 + col + 1] = acc[mi][n8][3];
        }
    }
    __syncthreads();

    for (int it = 0; it < 16; it++) {
        int m = it * 8 + wid;            // 0..127 local row
        int o = mt * 128 + m;            // global output channel
        float bo = __ldg(bias + o);
        float4 v = *(float4*)(Ds + m * 132 + lane * 4);
        v.x += bo; v.y += bo; v.z += bo; v.w += bo;
        *(float4*)(g_y + ((size_t)(b * DNOUT + o)) * 1024 + sg * 128 + lane * 4) = v;
        float s1 = v.x + v.y + v.z + v.w;
        float s2 = v.x * v.x + v.y * v.y + v.z * v.z + v.w * v.w;
        #pragma unroll
        for (int d = 16; d > 0; d >>= 1) {
            s1 += __shfl_xor_sync(0xffffffffu, s1, d);
            s2 += __shfl_xor_sync(0xffffffffu, s2, d);
        }
        if (lane == 0) {
            g_ps[o * NTILES + nt] = s1;
            g_pq[o * NTILES + nt] = s2;
        }
    }
}

// ---------------------------------------------------------------------------
// 6) BN stats finalize
// ---------------------------------------------------------------------------
__global__ void bnstat_kernel() {
    int o = blockIdx.x;
    int t = threadIdx.x;
    float s1 = 0.f, s2 = 0.f;
    for (int k = t; k < NTILES; k += 256) {
        s1 += g_ps[o * NTILES + k];
        s2 += g_pq[o * NTILES + k];
    }
    __shared__ float a[256], c[256];
    a[t] = s1; c[t] = s2;
    __syncthreads();
    for (int st = 128; st > 0; st >>= 1) {
        if (t < st) { a[t] += a[t + st]; c[t] += c[t + st]; }
        __syncthreads();
    }
    if (t == 0) {
        const float N = (float)(BS * NHALF * QOUT);
        float mean = a[0] / N;
        float var  = c[0] / N - mean * mean;
        g_mean[o] = mean;
        g_rstd[o] = rsqrtf(var + 1e-5f);
    }
}

// ---------------------------------------------------------------------------
// 7) Normalize + affine + tanh-GELU
// ---------------------------------------------------------------------------
__device__ __forceinline__ float gelu_tanh(float x) {
    float x3 = x * x * x;
    return 0.5f * x * (1.f + tanhf(0.7978845608028654f * (x + 0.044715f * x3)));
}
__global__ void norm_kernel(const float* __restrict__ gamma,
                            const float* __restrict__ beta,
                            float* __restrict__ out)
{
    const int TOT4 = YTOT / 4;
    int t = blockIdx.x * blockDim.x + threadIdx.x;
    if (t >= TOT4) return;
    int o = (t >> 8) & (DNOUT - 1);
    float r  = g_rstd[o];
    float m  = g_mean[o];
    float g  = gamma[o] * r;
    float bb = beta[o] - m * g;
    float4 v = ((const float4*)g_y)[t];
    float4 w;
    w.x = gelu_tanh(v.x * g + bb);
    w.y = gelu_tanh(v.y * g + bb);
    w.z = gelu_tanh(v.z * g + bb);
    w.w = gelu_tanh(v.w * g + bb);
    ((float4*)out)[t] = w;
}

// ---------------------------------------------------------------------------
// Launch
// ---------------------------------------------------------------------------
extern "C" void kernel_launch(void* const* d_in, const int* in_sizes, int n_in,
                              void* d_out, int out_size)
{
    const float* sparse_fea = (const float*)d_in[0];  // [64,256,64]
    const float* dense_fea  = (const float*)d_in[1];  // [64,128,4096]
    const float* stk_coor   = (const float*)d_in[2];  // [64,64,32]
    const float* conv_w     = (const float*)d_in[3];  // [256,128,1,3]
    const float* conv_b     = (const float*)d_in[4];  // [256]
    const float* bn_gamma   = (const float*)d_in[5];  // [256]
    const float* bn_beta    = (const float*)d_in[6];  // [256]

    float* out_sparse = (float*)d_out;
    float* out_dense  = out_sparse + BS * SPEMB * NHALF;
    float* out_coor   = out_dense + YTOT;

    cudaFuncSetAttribute(gemm_kernel,
                         cudaFuncAttributeMaxDynamicSharedMemorySize, SMEM_GEMM);

    fps_kernel<<<BS, NSTK>>>(stk_coor);
    wsplit_kernel<<<24, 256>>>(conv_w);

    gather_sparse_kernel<<<(BS * SPEMB * NHALF + 255) / 256, 256>>>(sparse_fea, out_sparse);
    gather_coor_kernel<<<(BS * NHALF * COORD + 255) / 256, 256>>>(stk_coor, out_coor);

    dim3 ggrid(NTILES, 2);
    gemm_kernel<<<ggrid, 256, SMEM_GEMM>>>(dense_fea, conv_b);

    bnstat_kernel<<<DNOUT, 256>>>();
    norm_kernel<<<(YTOT / 4 + 255) / 256, 256>>>(bn_gamma, bn_beta, out_dense);
}